// round 1
// baseline (speedup 1.0000x reference)
#include <cuda_runtime.h>

// Problem dims (fixed by the dataset; group_list is still read dynamically).
#define T_DIM 8192
#define K_DIM 4096
#define N_DIM 4096
#define R_DIM 64

// Scratch for the shrink result: shrink[T, R] fp32 (2 MB). Static __device__
// array — runtime allocation is forbidden by the harness.
__device__ float g_shrink[(size_t)T_DIM * R_DIM];

__device__ __forceinline__ int find_group(const int* __restrict__ gl,
                                          int n_groups, int token) {
    // group g = first index with token < gl[g]  (searchsorted 'right' semantics)
    int g = 0;
    while (g < n_groups - 1 && token >= gl[g]) g++;
    return g;
}

// ---------------------------------------------------------------------------
// Kernel 1: shrink[t, r] = sum_k x[t,k] * lora_a[g(t), r, k]
// Block: 128 tokens x 64 ranks, 256 threads, BK=16, 8x4 micro-tile.
// ---------------------------------------------------------------------------
__global__ __launch_bounds__(256) void shrink_kernel(
    const float* __restrict__ x, const float* __restrict__ lora_a,
    const int* __restrict__ gl, int n_groups)
{
    __shared__ float As[16][128];   // [k][token]
    __shared__ float Bs[16][64];    // [k][rank]

    const int tid  = threadIdx.x;
    const int row0 = blockIdx.x * 128;
    const int g    = find_group(gl, n_groups, row0);

    const float* A = x + (size_t)row0 * K_DIM;
    const float* B = lora_a + (size_t)g * R_DIM * K_DIM;

    const int ty = tid / 16;          // 0..15 : token octet
    const int tx = tid % 16;          // 0..15 : rank quad
    const int lr = tid / 4;           // 0..63 : load row
    const int lc = (tid % 4) * 4;     // 0,4,8,12 : load col (k)

    float acc[8][4];
    #pragma unroll
    for (int i = 0; i < 8; i++)
        #pragma unroll
        for (int j = 0; j < 4; j++) acc[i][j] = 0.f;

    for (int k0 = 0; k0 < K_DIM; k0 += 16) {
        float4 a0 = *(const float4*)(A + (size_t)lr        * K_DIM + k0 + lc);
        float4 a1 = *(const float4*)(A + (size_t)(lr + 64) * K_DIM + k0 + lc);
        float4 b0 = *(const float4*)(B + (size_t)lr        * K_DIM + k0 + lc);
        __syncthreads();
        As[lc + 0][lr]      = a0.x; As[lc + 1][lr]      = a0.y;
        As[lc + 2][lr]      = a0.z; As[lc + 3][lr]      = a0.w;
        As[lc + 0][lr + 64] = a1.x; As[lc + 1][lr + 64] = a1.y;
        As[lc + 2][lr + 64] = a1.z; As[lc + 3][lr + 64] = a1.w;
        Bs[lc + 0][lr] = b0.x; Bs[lc + 1][lr] = b0.y;
        Bs[lc + 2][lr] = b0.z; Bs[lc + 3][lr] = b0.w;
        __syncthreads();

        #pragma unroll
        for (int k = 0; k < 16; k++) {
            float4 av0 = *(const float4*)&As[k][ty * 8];
            float4 av1 = *(const float4*)&As[k][ty * 8 + 4];
            float4 bv  = *(const float4*)&Bs[k][tx * 4];
            float a[8] = {av0.x, av0.y, av0.z, av0.w, av1.x, av1.y, av1.z, av1.w};
            float b[4] = {bv.x, bv.y, bv.z, bv.w};
            #pragma unroll
            for (int i = 0; i < 8; i++)
                #pragma unroll
                for (int j = 0; j < 4; j++)
                    acc[i][j] = fmaf(a[i], b[j], acc[i][j]);
        }
    }

    #pragma unroll
    for (int i = 0; i < 8; i++) {
        float4 v = make_float4(acc[i][0], acc[i][1], acc[i][2], acc[i][3]);
        *(float4*)(&g_shrink[(size_t)(row0 + ty * 8 + i) * R_DIM + tx * 4]) = v;
    }
}

// ---------------------------------------------------------------------------
// Kernel 2: out[t,n] = sum_k x[t,k]*W[n,k]  +  sum_r shrink[t,r]*lora_b[g,r,n]
// Block: 128x128 tile, 256 threads, BK=8, 8x8 micro-tile.
// Expand is fused as 8 extra k-steps reusing the same SMEM/FMA loop.
// ---------------------------------------------------------------------------
__global__ __launch_bounds__(256) void main_kernel(
    const float* __restrict__ x, const float* __restrict__ W,
    const float* __restrict__ lora_b, const int* __restrict__ gl,
    int n_groups, float* __restrict__ out)
{
    __shared__ float As[8][128];    // [k][token]
    __shared__ float Bs[8][128];    // [k][n]

    const int tid  = threadIdx.x;
    const int row0 = blockIdx.y * 128;
    const int col0 = blockIdx.x * 128;

    const int ty = tid / 16;          // token octet
    const int tx = tid % 16;          // n octet
    const int lr = tid / 2;           // 0..127
    const int lc = (tid % 2) * 4;     // 0 or 4

    const float* Ax = x + (size_t)row0 * K_DIM;
    const float* Bw = W + (size_t)col0 * K_DIM;

    float acc[8][8];
    #pragma unroll
    for (int i = 0; i < 8; i++)
        #pragma unroll
        for (int j = 0; j < 8; j++) acc[i][j] = 0.f;

    // ---- base GEMM mainloop ----
    for (int k0 = 0; k0 < K_DIM; k0 += 8) {
        float4 av = *(const float4*)(Ax + (size_t)lr * K_DIM + k0 + lc);
        float4 bv = *(const float4*)(Bw + (size_t)lr * K_DIM + k0 + lc);
        __syncthreads();
        As[lc + 0][lr] = av.x; As[lc + 1][lr] = av.y;
        As[lc + 2][lr] = av.z; As[lc + 3][lr] = av.w;
        Bs[lc + 0][lr] = bv.x; Bs[lc + 1][lr] = bv.y;
        Bs[lc + 2][lr] = bv.z; Bs[lc + 3][lr] = bv.w;
        __syncthreads();

        #pragma unroll
        for (int k = 0; k < 8; k++) {
            float4 a0 = *(const float4*)&As[k][ty * 8];
            float4 a1 = *(const float4*)&As[k][ty * 8 + 4];
            float4 b0 = *(const float4*)&Bs[k][tx * 8];
            float4 b1 = *(const float4*)&Bs[k][tx * 8 + 4];
            float a[8] = {a0.x, a0.y, a0.z, a0.w, a1.x, a1.y, a1.z, a1.w};
            float b[8] = {b0.x, b0.y, b0.z, b0.w, b1.x, b1.y, b1.z, b1.w};
            #pragma unroll
            for (int i = 0; i < 8; i++)
                #pragma unroll
                for (int j = 0; j < 8; j++)
                    acc[i][j] = fmaf(a[i], b[j], acc[i][j]);
        }
    }

    // ---- fused LoRA expand: 8 more "k" steps over rank dimension ----
    const int g = find_group(gl, n_groups, row0);
    const float* S  = g_shrink + (size_t)row0 * R_DIM;
    const float* Bl = lora_b + (size_t)g * R_DIM * N_DIM + col0;
    const int er = tid / 32;          // 0..7   : r within chunk
    const int ec = (tid % 32) * 4;    // 0..124 : n

    for (int r0 = 0; r0 < R_DIM; r0 += 8) {
        float4 sv = *(const float4*)(S + (size_t)lr * R_DIM + r0 + lc);
        float4 lv = *(const float4*)(Bl + (size_t)(r0 + er) * N_DIM + ec);
        __syncthreads();
        As[lc + 0][lr] = sv.x; As[lc + 1][lr] = sv.y;
        As[lc + 2][lr] = sv.z; As[lc + 3][lr] = sv.w;
        *(float4*)&Bs[er][ec] = lv;
        __syncthreads();

        #pragma unroll
        for (int k = 0; k < 8; k++) {
            float4 a0 = *(const float4*)&As[k][ty * 8];
            float4 a1 = *(const float4*)&As[k][ty * 8 + 4];
            float4 b0 = *(const float4*)&Bs[k][tx * 8];
            float4 b1 = *(const float4*)&Bs[k][tx * 8 + 4];
            float a[8] = {a0.x, a0.y, a0.z, a0.w, a1.x, a1.y, a1.z, a1.w};
            float b[8] = {b0.x, b0.y, b0.z, b0.w, b1.x, b1.y, b1.z, b1.w};
            #pragma unroll
            for (int i = 0; i < 8; i++)
                #pragma unroll
                for (int j = 0; j < 8; j++)
                    acc[i][j] = fmaf(a[i], b[j], acc[i][j]);
        }
    }

    // ---- writeback (float4 x2 per row) ----
    #pragma unroll
    for (int i = 0; i < 8; i++) {
        float* orow = out + (size_t)(row0 + ty * 8 + i) * N_DIM + col0 + tx * 8;
        *(float4*)(orow)     = make_float4(acc[i][0], acc[i][1], acc[i][2], acc[i][3]);
        *(float4*)(orow + 4) = make_float4(acc[i][4], acc[i][5], acc[i][6], acc[i][7]);
    }
}

extern "C" void kernel_launch(void* const* d_in, const int* in_sizes, int n_in,
                              void* d_out, int out_size) {
    const float* x      = (const float*)d_in[0];
    const float* W      = (const float*)d_in[1];
    const float* lora_a = (const float*)d_in[2];
    const float* lora_b = (const float*)d_in[3];
    const int*   gl     = (const int*)d_in[4];
    const int n_groups  = in_sizes[4];
    float* out = (float*)d_out;

    shrink_kernel<<<T_DIM / 128, 256>>>(x, lora_a, gl, n_groups);
    main_kernel<<<dim3(N_DIM / 128, T_DIM / 128), 256>>>(x, W, lora_b, gl,
                                                         n_groups, out);
}

// round 5
// speedup vs baseline: 2.7041x; 2.7041x over previous
#include <cuda_runtime.h>
#include <cuda_bf16.h>
#include <cstdint>

#define T_DIM 8192
#define K_DIM 4096
#define N_DIM 4096
#define R_DIM 64
#define NGRP  8

// ---------------- static device scratch (alloc forbidden) -------------------
__device__ __nv_bfloat16 g_xh[(size_t)T_DIM * K_DIM];
__device__ __nv_bfloat16 g_xl[(size_t)T_DIM * K_DIM];
__device__ __nv_bfloat16 g_wh[(size_t)N_DIM * K_DIM];
__device__ __nv_bfloat16 g_wl[(size_t)N_DIM * K_DIM];
__device__ __nv_bfloat16 g_lah[(size_t)NGRP * R_DIM * K_DIM];
__device__ __nv_bfloat16 g_lal[(size_t)NGRP * R_DIM * K_DIM];
__device__ __nv_bfloat16 g_lbh[(size_t)NGRP * N_DIM * R_DIM];   // [g][n][r]
__device__ __nv_bfloat16 g_lbl[(size_t)NGRP * N_DIM * R_DIM];
__device__ __nv_bfloat16 g_shh[(size_t)T_DIM * R_DIM];
__device__ __nv_bfloat16 g_shl[(size_t)T_DIM * R_DIM];

// ---------------- asm helpers (base ISA only: sm_80-class) ------------------
__device__ __forceinline__ uint32_t smem_u32(const void* p) {
    uint32_t a;
    asm("{ .reg .u64 t; cvta.to.shared.u64 t, %1; cvt.u32.u64 %0, t; }"
        : "=r"(a) : "l"(p));
    return a;
}
#define CP16(dst, src) \
    asm volatile("cp.async.cg.shared.global [%0], [%1], 16;" :: "r"(dst), "l"(src))
#define CP_COMMIT() asm volatile("cp.async.commit_group;" ::: "memory")
#define CP_WAIT2()  asm volatile("cp.async.wait_group 2;"  ::: "memory")

#define LDSM4(d, addr) \
    asm volatile("ldmatrix.sync.aligned.m8n8.x4.shared.b16 {%0,%1,%2,%3}, [%4];" \
        : "=r"((d)[0]), "=r"((d)[1]), "=r"((d)[2]), "=r"((d)[3]) : "r"(addr))

#define MMA_BF16(ac, a, b0, b1) \
    asm volatile("mma.sync.aligned.m16n8k16.row.col.f32.bf16.bf16.f32 " \
        "{%0,%1,%2,%3}, {%4,%5,%6,%7}, {%8,%9}, {%0,%1,%2,%3};" \
        : "+f"((ac)[0]), "+f"((ac)[1]), "+f"((ac)[2]), "+f"((ac)[3]) \
        : "r"((a)[0]), "r"((a)[1]), "r"((a)[2]), "r"((a)[3]), "r"(b0), "r"(b1))

// smem byte offset of 16B chunk (row, ch) within a plane of 64B rows,
// XOR-swizzled so ldmatrix (8 rows x 16B per phase) is conflict-free.
__device__ __forceinline__ uint32_t swz(int row, int ch) {
    return (uint32_t)(row * 64 + ((ch ^ ((row >> 1) & 3)) << 4));
}

__device__ __forceinline__ int find_group(const int* __restrict__ gl,
                                          int n_groups, int token) {
    int g = 0;
    while (g < n_groups - 1 && token >= gl[g]) g++;
    return g;
}

__device__ __forceinline__ void split2(float v, __nv_bfloat16& h, __nv_bfloat16& l) {
    h = __float2bfloat16(v);
    l = __float2bfloat16(v - __bfloat162float(h));
}

// ---------------- pre-pass kernels ------------------------------------------
__global__ __launch_bounds__(256) void split_x_kernel(const float* __restrict__ in) {
    int i = blockIdx.x * 256 + threadIdx.x;
    float4 v = reinterpret_cast<const float4*>(in)[i];
    __nv_bfloat16 h0, h1, h2, h3, l0, l1, l2, l3;
    split2(v.x, h0, l0); split2(v.y, h1, l1);
    split2(v.z, h2, l2); split2(v.w, h3, l3);
    reinterpret_cast<__nv_bfloat162*>(g_xh)[2 * i]     = __halves2bfloat162(h0, h1);
    reinterpret_cast<__nv_bfloat162*>(g_xh)[2 * i + 1] = __halves2bfloat162(h2, h3);
    reinterpret_cast<__nv_bfloat162*>(g_xl)[2 * i]     = __halves2bfloat162(l0, l1);
    reinterpret_cast<__nv_bfloat162*>(g_xl)[2 * i + 1] = __halves2bfloat162(l2, l3);
}
__global__ __launch_bounds__(256) void split_w_kernel(const float* __restrict__ in) {
    int i = blockIdx.x * 256 + threadIdx.x;
    float4 v = reinterpret_cast<const float4*>(in)[i];
    __nv_bfloat16 h0, h1, h2, h3, l0, l1, l2, l3;
    split2(v.x, h0, l0); split2(v.y, h1, l1);
    split2(v.z, h2, l2); split2(v.w, h3, l3);
    reinterpret_cast<__nv_bfloat162*>(g_wh)[2 * i]     = __halves2bfloat162(h0, h1);
    reinterpret_cast<__nv_bfloat162*>(g_wh)[2 * i + 1] = __halves2bfloat162(h2, h3);
    reinterpret_cast<__nv_bfloat162*>(g_wl)[2 * i]     = __halves2bfloat162(l0, l1);
    reinterpret_cast<__nv_bfloat162*>(g_wl)[2 * i + 1] = __halves2bfloat162(l2, l3);
}
__global__ __launch_bounds__(256) void split_la_kernel(const float* __restrict__ in) {
    int i = blockIdx.x * 256 + threadIdx.x;
    float4 v = reinterpret_cast<const float4*>(in)[i];
    __nv_bfloat16 h0, h1, h2, h3, l0, l1, l2, l3;
    split2(v.x, h0, l0); split2(v.y, h1, l1);
    split2(v.z, h2, l2); split2(v.w, h3, l3);
    reinterpret_cast<__nv_bfloat162*>(g_lah)[2 * i]     = __halves2bfloat162(h0, h1);
    reinterpret_cast<__nv_bfloat162*>(g_lah)[2 * i + 1] = __halves2bfloat162(h2, h3);
    reinterpret_cast<__nv_bfloat162*>(g_lal)[2 * i]     = __halves2bfloat162(l0, l1);
    reinterpret_cast<__nv_bfloat162*>(g_lal)[2 * i + 1] = __halves2bfloat162(l2, l3);
}

// transpose+split lora_b[g][r][n] -> [g][n][r] hi/lo
__global__ __launch_bounds__(256) void lorab_t_kernel(const float* __restrict__ lb) {
    __shared__ float t[64][65];
    int g = blockIdx.y;
    int n0 = blockIdx.x * 64;
    for (int idx = threadIdx.x; idx < 4096; idx += 256) {
        int r = idx >> 6, n = idx & 63;
        t[n][r] = lb[((size_t)g * R_DIM + r) * N_DIM + n0 + n];
    }
    __syncthreads();
    for (int idx = threadIdx.x; idx < 4096; idx += 256) {
        int n = idx >> 6, r = idx & 63;
        __nv_bfloat16 h, l;
        split2(t[n][r], h, l);
        size_t o = ((size_t)g * N_DIM + n0 + n) * R_DIM + r;
        g_lbh[o] = h; g_lbl[o] = l;
    }
}

// =============================================================================
// Shrink GEMM: shrink[8192,64] = x @ lora_a[g]^T, 3-term bf16 split.
// CTA tile 128x64, 256 threads (8 warps: 4m x 2n, warp tile 32x32), BK=32.
// Stage: Ah(8K) Al(8K) Bh(4K) Bl(4K) = 24KB; 4 stages = 96KB.
// =============================================================================
#define SH_STAGE 24576
#define SH_CHUNKS (K_DIM / 32)   // 128

__global__ __launch_bounds__(256, 1) void shrink_gemm(
    const int* __restrict__ gl, int n_groups)
{
    extern __shared__ char smem[];
    uint32_t sb = smem_u32(smem);
    int tid = threadIdx.x, lane = tid & 31, w = tid >> 5;
    int m_off = (w & 3) * 32, n_off = (w >> 2) * 32;
    int row0 = blockIdx.x * 128;
    int g = find_group(gl, n_groups, row0);

    const __nv_bfloat16* Ah = g_xh + (size_t)row0 * K_DIM;
    const __nv_bfloat16* Al = g_xl + (size_t)row0 * K_DIM;
    const __nv_bfloat16* Bh = g_lah + (size_t)g * R_DIM * K_DIM;
    const __nv_bfloat16* Bl = g_lal + (size_t)g * R_DIM * K_DIM;

    // acc[mt][j] : mt = m 16-block (2), j = n8 block (4 -> 32 n-cols)
    float acc[2][4][4];
    #pragma unroll
    for (int i = 0; i < 2; i++)
        #pragma unroll
        for (int j = 0; j < 4; j++)
            #pragma unroll
            for (int q = 0; q < 4; q++) acc[i][j][q] = 0.f;

    // fill stage s with chunk c (k-offset c*32): 1536 16B items, 6 per thread
    auto fill = [&](int s, int c) {
        uint32_t st = sb + s * SH_STAGE;
        #pragma unroll
        for (int it = 0; it < 6; it++) {
            int idx = tid + it * 256;
            if (idx < 1024) {               // A planes: 512 items each
                int pl = idx >> 9, u = idx & 511;
                int row = u >> 2, ch = u & 3;
                const __nv_bfloat16* src = (pl ? Al : Ah)
                    + (size_t)row * K_DIM + c * 32 + ch * 8;
                CP16(st + pl * 8192 + swz(row, ch), src);
            } else {                        // B planes: 256 items each
                int v = idx - 1024;
                int pl = v >> 8, u = v & 255;
                int row = u >> 2, ch = u & 3;
                const __nv_bfloat16* src = (pl ? Bl : Bh)
                    + (size_t)row * K_DIM + c * 32 + ch * 8;
                CP16(st + 16384 + pl * 4096 + swz(row, ch), src);
            }
        }
    };

    fill(0, 0); CP_COMMIT();
    fill(1, 1); CP_COMMIT();
    fill(2, 2); CP_COMMIT();

    for (int c = 0; c < SH_CHUNKS; c++) {
        CP_WAIT2();
        __syncthreads();
        uint32_t st = sb + (c & 3) * SH_STAGE;
        #pragma unroll
        for (int ks = 0; ks < 2; ks++) {
            uint32_t ah[2][4], al[2][4], bb[2][4];
            #pragma unroll
            for (int mt = 0; mt < 2; mt++) {
                int row = m_off + mt * 16 + (lane & 15);
                int ch = ks * 2 + (lane >> 4);
                uint32_t ad = st + swz(row, ch);
                LDSM4(ah[mt], ad);
                LDSM4(al[mt], ad + 8192);
            }
            // B hi plane: full 32-col warp tile (2 x ldmatrix.x4)
            #pragma unroll
            for (int p = 0; p < 2; p++) {
                int row = n_off + p * 16 + (lane & 15);
                int ch = ks * 2 + (lane >> 4);
                LDSM4(bb[p], st + 16384 + swz(row, ch));
            }
            #pragma unroll
            for (int mt = 0; mt < 2; mt++)
                #pragma unroll
                for (int p = 0; p < 2; p++) {
                    MMA_BF16(acc[mt][2 * p],     ah[mt], bb[p][0], bb[p][2]);
                    MMA_BF16(acc[mt][2 * p + 1], ah[mt], bb[p][1], bb[p][3]);
                    MMA_BF16(acc[mt][2 * p],     al[mt], bb[p][0], bb[p][2]);
                    MMA_BF16(acc[mt][2 * p + 1], al[mt], bb[p][1], bb[p][3]);
                }
            // B lo plane (hi A only)
            #pragma unroll
            for (int p = 0; p < 2; p++) {
                int row = n_off + p * 16 + (lane & 15);
                int ch = ks * 2 + (lane >> 4);
                LDSM4(bb[p], st + 16384 + 4096 + swz(row, ch));
            }
            #pragma unroll
            for (int mt = 0; mt < 2; mt++)
                #pragma unroll
                for (int p = 0; p < 2; p++) {
                    MMA_BF16(acc[mt][2 * p],     ah[mt], bb[p][0], bb[p][2]);
                    MMA_BF16(acc[mt][2 * p + 1], ah[mt], bb[p][1], bb[p][3]);
                }
        }
        __syncthreads();
        if (c + 3 < SH_CHUNKS) fill((c + 3) & 3, c + 3);
        CP_COMMIT();
    }

    #pragma unroll
    for (int mt = 0; mt < 2; mt++)
        #pragma unroll
        for (int j = 0; j < 4; j++) {
            int row = row0 + m_off + mt * 16 + (lane >> 2);
            int col = n_off + j * 8 + ((lane & 3) << 1);
            __nv_bfloat16 h0, l0, h1, l1;
            split2(acc[mt][j][0], h0, l0); split2(acc[mt][j][1], h1, l1);
            *reinterpret_cast<__nv_bfloat162*>(g_shh + (size_t)row * R_DIM + col)
                = __halves2bfloat162(h0, h1);
            *reinterpret_cast<__nv_bfloat162*>(g_shl + (size_t)row * R_DIM + col)
                = __halves2bfloat162(l0, l1);
            split2(acc[mt][j][2], h0, l0); split2(acc[mt][j][3], h1, l1);
            *reinterpret_cast<__nv_bfloat162*>(g_shh + (size_t)(row + 8) * R_DIM + col)
                = __halves2bfloat162(h0, h1);
            *reinterpret_cast<__nv_bfloat162*>(g_shl + (size_t)(row + 8) * R_DIM + col)
                = __halves2bfloat162(l0, l1);
        }
}

// =============================================================================
// Main GEMM: out[8192,4096] = x @ W^T (+ fused LoRA expand over rank 64).
// CTA tile 128x256, 512 threads (16 warps: 4m x 4n, warp tile 32x64), BK=32.
// Stage: Ah(8K) Al(8K) Bh(16K) Bl(16K) = 48KB; 4 stages = 192KB.
// Chunks: 128 base-K + 2 LoRA (rank 64).
// =============================================================================
#define MN_STAGE 49152
#define MN_CHUNKS (K_DIM / 32 + 2)   // 130

__global__ __launch_bounds__(512, 1) void gemm_main(
    const int* __restrict__ gl, int n_groups, float* __restrict__ out)
{
    extern __shared__ char smem[];
    uint32_t sb = smem_u32(smem);
    int tid = threadIdx.x, lane = tid & 31, w = tid >> 5;
    int m_off = (w & 3) * 32, n_off = (w >> 2) * 64;
    int row0 = blockIdx.y * 128;
    int col0 = blockIdx.x * 256;
    int g = find_group(gl, n_groups, row0);

    float acc[2][8][4];
    #pragma unroll
    for (int i = 0; i < 2; i++)
        #pragma unroll
        for (int j = 0; j < 8; j++)
            #pragma unroll
            for (int q = 0; q < 4; q++) acc[i][j][q] = 0.f;

    auto fill = [&](int s, int c) {
        uint32_t st = sb + s * MN_STAGE;
        const __nv_bfloat16 *pAh, *pAl, *pBh, *pBl;
        size_t lda, ldb;
        if (c < K_DIM / 32) {
            pAh = g_xh + (size_t)row0 * K_DIM + c * 32;
            pAl = g_xl + (size_t)row0 * K_DIM + c * 32;
            pBh = g_wh + (size_t)col0 * K_DIM + c * 32;
            pBl = g_wl + (size_t)col0 * K_DIM + c * 32;
            lda = K_DIM; ldb = K_DIM;
        } else {
            int kk = (c - K_DIM / 32) * 32;
            pAh = g_shh + (size_t)row0 * R_DIM + kk;
            pAl = g_shl + (size_t)row0 * R_DIM + kk;
            pBh = g_lbh + ((size_t)g * N_DIM + col0) * R_DIM + kk;
            pBl = g_lbl + ((size_t)g * N_DIM + col0) * R_DIM + kk;
            lda = R_DIM; ldb = R_DIM;
        }
        #pragma unroll
        for (int it = 0; it < 6; it++) {
            int idx = tid + it * 512;
            if (idx < 1024) {               // A planes: 512 items each
                int pl = idx >> 9, u = idx & 511;
                int row = u >> 2, ch = u & 3;
                const __nv_bfloat16* src = (pl ? pAl : pAh)
                    + (size_t)row * lda + ch * 8;
                CP16(st + pl * 8192 + swz(row, ch), src);
            } else {                        // B planes: 1024 items each
                int v = idx - 1024;
                int pl = v >> 10, u = v & 1023;
                int row = u >> 2, ch = u & 3;
                const __nv_bfloat16* src = (pl ? pBl : pBh)
                    + (size_t)row * ldb + ch * 8;
                CP16(st + 16384 + pl * 16384 + swz(row, ch), src);
            }
        }
    };

    fill(0, 0); CP_COMMIT();
    fill(1, 1); CP_COMMIT();
    fill(2, 2); CP_COMMIT();

    for (int c = 0; c < MN_CHUNKS; c++) {
        CP_WAIT2();
        __syncthreads();
        uint32_t st = sb + (c & 3) * MN_STAGE;
        #pragma unroll
        for (int ks = 0; ks < 2; ks++) {
            uint32_t ah[2][4], al[2][4], bb[4][4];
            #pragma unroll
            for (int mt = 0; mt < 2; mt++) {
                int row = m_off + mt * 16 + (lane & 15);
                int ch = ks * 2 + (lane >> 4);
                uint32_t ad = st + swz(row, ch);
                LDSM4(ah[mt], ad);
                LDSM4(al[mt], ad + 8192);
            }
            // B hi plane: 4 x ldmatrix.x4 covering n_off..n_off+63
            #pragma unroll
            for (int p = 0; p < 4; p++) {
                int row = n_off + p * 16 + (lane & 15);
                int ch = ks * 2 + (lane >> 4);
                LDSM4(bb[p], st + 16384 + swz(row, ch));
            }
            #pragma unroll
            for (int mt = 0; mt < 2; mt++)
                #pragma unroll
                for (int p = 0; p < 4; p++) {
                    MMA_BF16(acc[mt][2 * p],     ah[mt], bb[p][0], bb[p][2]);
                    MMA_BF16(acc[mt][2 * p + 1], ah[mt], bb[p][1], bb[p][3]);
                    MMA_BF16(acc[mt][2 * p],     al[mt], bb[p][0], bb[p][2]);
                    MMA_BF16(acc[mt][2 * p + 1], al[mt], bb[p][1], bb[p][3]);
                }
            // B lo plane (reuse bb regs)
            #pragma unroll
            for (int p = 0; p < 4; p++) {
                int row = n_off + p * 16 + (lane & 15);
                int ch = ks * 2 + (lane >> 4);
                LDSM4(bb[p], st + 32768 + swz(row, ch));
            }
            #pragma unroll
            for (int mt = 0; mt < 2; mt++)
                #pragma unroll
                for (int p = 0; p < 4; p++) {
                    MMA_BF16(acc[mt][2 * p],     ah[mt], bb[p][0], bb[p][2]);
                    MMA_BF16(acc[mt][2 * p + 1], ah[mt], bb[p][1], bb[p][3]);
                }
        }
        __syncthreads();
        if (c + 3 < MN_CHUNKS) fill((c + 3) & 3, c + 3);
        CP_COMMIT();
    }

    #pragma unroll
    for (int mt = 0; mt < 2; mt++)
        #pragma unroll
        for (int j = 0; j < 8; j++) {
            int row = row0 + m_off + mt * 16 + (lane >> 2);
            int col = col0 + n_off + j * 8 + ((lane & 3) << 1);
            *reinterpret_cast<float2*>(out + (size_t)row * N_DIM + col)
                = make_float2(acc[mt][j][0], acc[mt][j][1]);
            *reinterpret_cast<float2*>(out + (size_t)(row + 8) * N_DIM + col)
                = make_float2(acc[mt][j][2], acc[mt][j][3]);
        }
}

// ---------------- launch -----------------------------------------------------
extern "C" void kernel_launch(void* const* d_in, const int* in_sizes, int n_in,
                              void* d_out, int out_size) {
    const float* x      = (const float*)d_in[0];
    const float* W      = (const float*)d_in[1];
    const float* lora_a = (const float*)d_in[2];
    const float* lora_b = (const float*)d_in[3];
    const int*   gl     = (const int*)d_in[4];
    const int n_groups  = in_sizes[4];
    float* out = (float*)d_out;

    cudaFuncSetAttribute(shrink_gemm, cudaFuncAttributeMaxDynamicSharedMemorySize,
                         4 * SH_STAGE);
    cudaFuncSetAttribute(gemm_main, cudaFuncAttributeMaxDynamicSharedMemorySize,
                         4 * MN_STAGE);

    split_x_kernel<<<(T_DIM * (size_t)K_DIM / 4) / 256, 256>>>(x);
    split_w_kernel<<<(N_DIM * (size_t)K_DIM / 4) / 256, 256>>>(W);
    split_la_kernel<<<((size_t)NGRP * R_DIM * K_DIM / 4) / 256, 256>>>(lora_a);
    lorab_t_kernel<<<dim3(N_DIM / 64, NGRP), 256>>>(lora_b);

    shrink_gemm<<<T_DIM / 128, 256, 4 * SH_STAGE>>>(gl, n_groups);
    gemm_main<<<dim3(N_DIM / 256, T_DIM / 128), 512, 4 * MN_STAGE>>>(
        gl, n_groups, out);
}

// round 6
// speedup vs baseline: 6.5914x; 2.4376x over previous
#include <cuda_runtime.h>
#include <cuda_fp16.h>
#include <cstdint>

#define T_DIM 8192
#define K_DIM 4096
#define N_DIM 4096
#define R_DIM 64
#define NGRP  8

// ---------------- static device scratch (alloc forbidden) -------------------
__device__ __half g_x16[(size_t)T_DIM * K_DIM];
__device__ __half g_w16[(size_t)N_DIM * K_DIM];
__device__ __half g_la16[(size_t)NGRP * R_DIM * K_DIM];
__device__ __half g_lb16[(size_t)NGRP * N_DIM * R_DIM];   // [g][n][r] transposed
__device__ __half g_sh16[(size_t)T_DIM * R_DIM];

// ---------------- asm helpers (base ISA only: sm_80-class) ------------------
__device__ __forceinline__ uint32_t smem_u32(const void* p) {
    uint32_t a;
    asm("{ .reg .u64 t; cvta.to.shared.u64 t, %1; cvt.u32.u64 %0, t; }"
        : "=r"(a) : "l"(p));
    return a;
}
#define CP16(dst, src) \
    asm volatile("cp.async.cg.shared.global [%0], [%1], 16;" :: "r"(dst), "l"(src))
#define CP_COMMIT() asm volatile("cp.async.commit_group;" ::: "memory")
#define CP_WAIT2()  asm volatile("cp.async.wait_group 2;"  ::: "memory")

#define LDSM4(d, addr) \
    asm volatile("ldmatrix.sync.aligned.m8n8.x4.shared.b16 {%0,%1,%2,%3}, [%4];" \
        : "=r"((d)[0]), "=r"((d)[1]), "=r"((d)[2]), "=r"((d)[3]) : "r"(addr))

#define MMA_F16(ac, a, b0, b1) \
    asm volatile("mma.sync.aligned.m16n8k16.row.col.f32.f16.f16.f32 " \
        "{%0,%1,%2,%3}, {%4,%5,%6,%7}, {%8,%9}, {%0,%1,%2,%3};" \
        : "+f"((ac)[0]), "+f"((ac)[1]), "+f"((ac)[2]), "+f"((ac)[3]) \
        : "r"((a)[0]), "r"((a)[1]), "r"((a)[2]), "r"((a)[3]), "r"(b0), "r"(b1))

// smem byte offset of 16B chunk (row, ch) within a plane of 64B rows,
// XOR-swizzled so ldmatrix (8 rows x 16B per phase) is conflict-free.
__device__ __forceinline__ uint32_t swz(int row, int ch) {
    return (uint32_t)(row * 64 + ((ch ^ ((row >> 1) & 3)) << 4));
}

__device__ __forceinline__ int find_group(const int* __restrict__ gl,
                                          int n_groups, int token) {
    int g = 0;
    while (g < n_groups - 1 && token >= gl[g]) g++;
    return g;
}

// ---------------- pre-pass kernels ------------------------------------------
__global__ __launch_bounds__(256) void cvt_x_kernel(const float* __restrict__ in) {
    int i = blockIdx.x * 256 + threadIdx.x;
    float4 v = reinterpret_cast<const float4*>(in)[i];
    reinterpret_cast<__half2*>(g_x16)[2 * i]     = __floats2half2_rn(v.x, v.y);
    reinterpret_cast<__half2*>(g_x16)[2 * i + 1] = __floats2half2_rn(v.z, v.w);
}
__global__ __launch_bounds__(256) void cvt_w_kernel(const float* __restrict__ in) {
    int i = blockIdx.x * 256 + threadIdx.x;
    float4 v = reinterpret_cast<const float4*>(in)[i];
    reinterpret_cast<__half2*>(g_w16)[2 * i]     = __floats2half2_rn(v.x, v.y);
    reinterpret_cast<__half2*>(g_w16)[2 * i + 1] = __floats2half2_rn(v.z, v.w);
}
__global__ __launch_bounds__(256) void cvt_la_kernel(const float* __restrict__ in) {
    int i = blockIdx.x * 256 + threadIdx.x;
    float4 v = reinterpret_cast<const float4*>(in)[i];
    reinterpret_cast<__half2*>(g_la16)[2 * i]     = __floats2half2_rn(v.x, v.y);
    reinterpret_cast<__half2*>(g_la16)[2 * i + 1] = __floats2half2_rn(v.z, v.w);
}

// transpose lora_b[g][r][n] -> [g][n][r] fp16
__global__ __launch_bounds__(256) void lorab_t_kernel(const float* __restrict__ lb) {
    __shared__ float t[64][65];
    int g = blockIdx.y;
    int n0 = blockIdx.x * 64;
    for (int idx = threadIdx.x; idx < 4096; idx += 256) {
        int r = idx >> 6, n = idx & 63;
        t[n][r] = lb[((size_t)g * R_DIM + r) * N_DIM + n0 + n];
    }
    __syncthreads();
    for (int idx = threadIdx.x; idx < 4096; idx += 256) {
        int n = idx >> 6, r = idx & 63;
        g_lb16[((size_t)g * N_DIM + n0 + n) * R_DIM + r] = __float2half_rn(t[n][r]);
    }
}

// =============================================================================
// Shrink GEMM: shrink[8192,64] = x @ lora_a[g]^T, single fp16 term.
// CTA tile 128x64, 256 threads (8 warps: 4m x 2n, warp tile 32x32), BK=32.
// Stage: A(8K) B(4K) = 12KB; 4 stages = 48KB.
// =============================================================================
#define SH_STAGE 12288
#define SH_CHUNKS (K_DIM / 32)   // 128

__global__ __launch_bounds__(256, 1) void shrink_gemm(
    const int* __restrict__ gl, int n_groups)
{
    extern __shared__ char smem[];
    uint32_t sb = smem_u32(smem);
    int tid = threadIdx.x, lane = tid & 31, w = tid >> 5;
    int m_off = (w & 3) * 32, n_off = (w >> 2) * 32;
    int row0 = blockIdx.x * 128;
    int g = find_group(gl, n_groups, row0);

    const __half* A = g_x16 + (size_t)row0 * K_DIM;
    const __half* B = g_la16 + (size_t)g * R_DIM * K_DIM;

    // acc[mt][j] : mt = m 16-block (2), j = n8 block (4 -> 32 n-cols)
    float acc[2][4][4];
    #pragma unroll
    for (int i = 0; i < 2; i++)
        #pragma unroll
        for (int j = 0; j < 4; j++)
            #pragma unroll
            for (int q = 0; q < 4; q++) acc[i][j][q] = 0.f;

    // fill stage s with chunk c (k-offset c*32): 768 16B items, 3 per thread
    auto fill = [&](int s, int c) {
        uint32_t st = sb + s * SH_STAGE;
        #pragma unroll
        for (int it = 0; it < 3; it++) {
            int idx = tid + it * 256;
            if (idx < 512) {                // A: 128 rows x 4 ch
                int row = idx >> 2, ch = idx & 3;
                CP16(st + swz(row, ch),
                     A + (size_t)row * K_DIM + c * 32 + ch * 8);
            } else {                        // B: 64 rows x 4 ch
                int u = idx - 512;
                int row = u >> 2, ch = u & 3;
                CP16(st + 8192 + swz(row, ch),
                     B + (size_t)row * K_DIM + c * 32 + ch * 8);
            }
        }
    };

    fill(0, 0); CP_COMMIT();
    fill(1, 1); CP_COMMIT();
    fill(2, 2); CP_COMMIT();

    for (int c = 0; c < SH_CHUNKS; c++) {
        CP_WAIT2();
        __syncthreads();
        uint32_t st = sb + (c & 3) * SH_STAGE;
        #pragma unroll
        for (int ks = 0; ks < 2; ks++) {
            uint32_t aa[2][4], bb[2][4];
            #pragma unroll
            for (int mt = 0; mt < 2; mt++) {
                int row = m_off + mt * 16 + (lane & 15);
                int ch = ks * 2 + (lane >> 4);
                LDSM4(aa[mt], st + swz(row, ch));
            }
            #pragma unroll
            for (int p = 0; p < 2; p++) {
                int row = n_off + p * 16 + (lane & 15);
                int ch = ks * 2 + (lane >> 4);
                LDSM4(bb[p], st + 8192 + swz(row, ch));
            }
            #pragma unroll
            for (int mt = 0; mt < 2; mt++)
                #pragma unroll
                for (int p = 0; p < 2; p++) {
                    MMA_F16(acc[mt][2 * p],     aa[mt], bb[p][0], bb[p][2]);
                    MMA_F16(acc[mt][2 * p + 1], aa[mt], bb[p][1], bb[p][3]);
                }
        }
        __syncthreads();
        if (c + 3 < SH_CHUNKS) fill((c + 3) & 3, c + 3);
        CP_COMMIT();
    }

    #pragma unroll
    for (int mt = 0; mt < 2; mt++)
        #pragma unroll
        for (int j = 0; j < 4; j++) {
            int row = row0 + m_off + mt * 16 + (lane >> 2);
            int col = n_off + j * 8 + ((lane & 3) << 1);
            *reinterpret_cast<__half2*>(g_sh16 + (size_t)row * R_DIM + col)
                = __floats2half2_rn(acc[mt][j][0], acc[mt][j][1]);
            *reinterpret_cast<__half2*>(g_sh16 + (size_t)(row + 8) * R_DIM + col)
                = __floats2half2_rn(acc[mt][j][2], acc[mt][j][3]);
        }
}

// =============================================================================
// Main GEMM: out[8192,4096] = x @ W^T (+ fused LoRA expand over rank 64).
// CTA tile 128x256, 512 threads (16 warps: 4m x 4n, warp tile 32x64), BK=32.
// Stage: A(8K) B(16K) = 24KB; 4 stages = 96KB.
// Chunks: 128 base-K + 2 LoRA (rank 64).
// =============================================================================
#define MN_STAGE 24576
#define MN_CHUNKS (K_DIM / 32 + 2)   // 130

__global__ __launch_bounds__(512, 1) void gemm_main(
    const int* __restrict__ gl, int n_groups, float* __restrict__ out)
{
    extern __shared__ char smem[];
    uint32_t sb = smem_u32(smem);
    int tid = threadIdx.x, lane = tid & 31, w = tid >> 5;
    int m_off = (w & 3) * 32, n_off = (w >> 2) * 64;
    int row0 = blockIdx.y * 128;
    int col0 = blockIdx.x * 256;
    int g = find_group(gl, n_groups, row0);

    float acc[2][8][4];
    #pragma unroll
    for (int i = 0; i < 2; i++)
        #pragma unroll
        for (int j = 0; j < 8; j++)
            #pragma unroll
            for (int q = 0; q < 4; q++) acc[i][j][q] = 0.f;

    auto fill = [&](int s, int c) {
        uint32_t st = sb + s * MN_STAGE;
        const __half *pA, *pB;
        size_t lda, ldb;
        if (c < K_DIM / 32) {
            pA = g_x16 + (size_t)row0 * K_DIM + c * 32;
            pB = g_w16 + (size_t)col0 * K_DIM + c * 32;
            lda = K_DIM; ldb = K_DIM;
        } else {
            int kk = (c - K_DIM / 32) * 32;
            pA = g_sh16 + (size_t)row0 * R_DIM + kk;
            pB = g_lb16 + ((size_t)g * N_DIM + col0) * R_DIM + kk;
            lda = R_DIM; ldb = R_DIM;
        }
        #pragma unroll
        for (int it = 0; it < 3; it++) {
            int idx = tid + it * 512;
            if (idx < 512) {                // A: 128 rows x 4 ch
                int row = idx >> 2, ch = idx & 3;
                CP16(st + swz(row, ch), pA + (size_t)row * lda + ch * 8);
            } else {                        // B: 256 rows x 4 ch
                int u = idx - 512;
                int row = u >> 2, ch = u & 3;
                CP16(st + 8192 + swz(row, ch), pB + (size_t)row * ldb + ch * 8);
            }
        }
    };

    fill(0, 0); CP_COMMIT();
    fill(1, 1); CP_COMMIT();
    fill(2, 2); CP_COMMIT();

    for (int c = 0; c < MN_CHUNKS; c++) {
        CP_WAIT2();
        __syncthreads();
        uint32_t st = sb + (c & 3) * MN_STAGE;
        #pragma unroll
        for (int ks = 0; ks < 2; ks++) {
            uint32_t aa[2][4], bb[4][4];
            #pragma unroll
            for (int mt = 0; mt < 2; mt++) {
                int row = m_off + mt * 16 + (lane & 15);
                int ch = ks * 2 + (lane >> 4);
                LDSM4(aa[mt], st + swz(row, ch));
            }
            #pragma unroll
            for (int p = 0; p < 4; p++) {
                int row = n_off + p * 16 + (lane & 15);
                int ch = ks * 2 + (lane >> 4);
                LDSM4(bb[p], st + 8192 + swz(row, ch));
            }
            #pragma unroll
            for (int mt = 0; mt < 2; mt++)
                #pragma unroll
                for (int p = 0; p < 4; p++) {
                    MMA_F16(acc[mt][2 * p],     aa[mt], bb[p][0], bb[p][2]);
                    MMA_F16(acc[mt][2 * p + 1], aa[mt], bb[p][1], bb[p][3]);
                }
        }
        __syncthreads();
        if (c + 3 < MN_CHUNKS) fill((c + 3) & 3, c + 3);
        CP_COMMIT();
    }

    #pragma unroll
    for (int mt = 0; mt < 2; mt++)
        #pragma unroll
        for (int j = 0; j < 8; j++) {
            int row = row0 + m_off + mt * 16 + (lane >> 2);
            int col = col0 + n_off + j * 8 + ((lane & 3) << 1);
            *reinterpret_cast<float2*>(out + (size_t)row * N_DIM + col)
                = make_float2(acc[mt][j][0], acc[mt][j][1]);
            *reinterpret_cast<float2*>(out + (size_t)(row + 8) * N_DIM + col)
                = make_float2(acc[mt][j][2], acc[mt][j][3]);
        }
}

// ---------------- launch -----------------------------------------------------
extern "C" void kernel_launch(void* const* d_in, const int* in_sizes, int n_in,
                              void* d_out, int out_size) {
    const float* x      = (const float*)d_in[0];
    const float* W      = (const float*)d_in[1];
    const float* lora_a = (const float*)d_in[2];
    const float* lora_b = (const float*)d_in[3];
    const int*   gl     = (const int*)d_in[4];
    const int n_groups  = in_sizes[4];
    float* out = (float*)d_out;

    cudaFuncSetAttribute(shrink_gemm, cudaFuncAttributeMaxDynamicSharedMemorySize,
                         4 * SH_STAGE);
    cudaFuncSetAttribute(gemm_main, cudaFuncAttributeMaxDynamicSharedMemorySize,
                         4 * MN_STAGE);

    cvt_x_kernel<<<(T_DIM * (size_t)K_DIM / 4) / 256, 256>>>(x);
    cvt_w_kernel<<<(N_DIM * (size_t)K_DIM / 4) / 256, 256>>>(W);
    cvt_la_kernel<<<((size_t)NGRP * R_DIM * K_DIM / 4) / 256, 256>>>(lora_a);
    lorab_t_kernel<<<dim3(N_DIM / 64, NGRP), 256>>>(lora_b);

    shrink_gemm<<<T_DIM / 128, 256, 4 * SH_STAGE>>>(gl, n_groups);
    gemm_main<<<dim3(N_DIM / 256, T_DIM / 128), 512, 4 * MN_STAGE>>>(
        gl, n_groups, out);
}

// round 7
// speedup vs baseline: 7.6700x; 1.1636x over previous
#include <cuda_runtime.h>
#include <cuda_fp16.h>
#include <cstdint>

#define T_DIM 8192
#define K_DIM 4096
#define N_DIM 4096
#define R_DIM 64
#define NGRP  8

// ---------------- static device scratch (alloc forbidden) -------------------
__device__ __half g_x16[(size_t)T_DIM * K_DIM];
__device__ __half g_w16[(size_t)N_DIM * K_DIM];
__device__ __half g_la16[(size_t)NGRP * R_DIM * K_DIM];
__device__ __half g_lb16[(size_t)NGRP * N_DIM * R_DIM];   // [g][n][r] transposed
__device__ __half g_sh16[(size_t)T_DIM * R_DIM];

// ---------------- asm helpers (base ISA only: sm_80-class) ------------------
__device__ __forceinline__ uint32_t smem_u32(const void* p) {
    uint32_t a;
    asm("{ .reg .u64 t; cvta.to.shared.u64 t, %1; cvt.u32.u64 %0, t; }"
        : "=r"(a) : "l"(p));
    return a;
}
#define CP16(dst, src) \
    asm volatile("cp.async.cg.shared.global [%0], [%1], 16;" :: "r"(dst), "l"(src))
#define CP_COMMIT() asm volatile("cp.async.commit_group;" ::: "memory")
#define CP_WAIT2()  asm volatile("cp.async.wait_group 2;"  ::: "memory")

#define LDSM4(d, addr) \
    asm volatile("ldmatrix.sync.aligned.m8n8.x4.shared.b16 {%0,%1,%2,%3}, [%4];" \
        : "=r"((d)[0]), "=r"((d)[1]), "=r"((d)[2]), "=r"((d)[3]) : "r"(addr))

#define MMA_F16(ac, a, b0, b1) \
    asm volatile("mma.sync.aligned.m16n8k16.row.col.f32.f16.f16.f32 " \
        "{%0,%1,%2,%3}, {%4,%5,%6,%7}, {%8,%9}, {%0,%1,%2,%3};" \
        : "+f"((ac)[0]), "+f"((ac)[1]), "+f"((ac)[2]), "+f"((ac)[3]) \
        : "r"((a)[0]), "r"((a)[1]), "r"((a)[2]), "r"((a)[3]), "r"(b0), "r"(b1))

// smem byte offset of 16B chunk (row, ch) within a tile of 128B rows (BK=64
// halves). Full 8-way XOR swizzle: ldmatrix (8 rows, same ch) hits 8 distinct
// 16B banks; a 128B row store covers the full row permuted.
__device__ __forceinline__ uint32_t swz(int row, int ch) {
    return (uint32_t)((row << 7) | (((ch ^ (row & 7)) & 7) << 4));
}

__device__ __forceinline__ int find_group(const int* __restrict__ gl,
                                          int n_groups, int token) {
    int g = 0;
    while (g < n_groups - 1 && token >= gl[g]) g++;
    return g;
}

// ---------------- pre-pass kernels ------------------------------------------
__global__ __launch_bounds__(256) void cvt_x_kernel(const float* __restrict__ in) {
    int i = blockIdx.x * 256 + threadIdx.x;
    float4 v = reinterpret_cast<const float4*>(in)[i];
    reinterpret_cast<__half2*>(g_x16)[2 * i]     = __floats2half2_rn(v.x, v.y);
    reinterpret_cast<__half2*>(g_x16)[2 * i + 1] = __floats2half2_rn(v.z, v.w);
}
__global__ __launch_bounds__(256) void cvt_w_kernel(const float* __restrict__ in) {
    int i = blockIdx.x * 256 + threadIdx.x;
    float4 v = reinterpret_cast<const float4*>(in)[i];
    reinterpret_cast<__half2*>(g_w16)[2 * i]     = __floats2half2_rn(v.x, v.y);
    reinterpret_cast<__half2*>(g_w16)[2 * i + 1] = __floats2half2_rn(v.z, v.w);
}
__global__ __launch_bounds__(256) void cvt_la_kernel(const float* __restrict__ in) {
    int i = blockIdx.x * 256 + threadIdx.x;
    float4 v = reinterpret_cast<const float4*>(in)[i];
    reinterpret_cast<__half2*>(g_la16)[2 * i]     = __floats2half2_rn(v.x, v.y);
    reinterpret_cast<__half2*>(g_la16)[2 * i + 1] = __floats2half2_rn(v.z, v.w);
}

// transpose lora_b[g][r][n] -> [g][n][r] fp16
__global__ __launch_bounds__(256) void lorab_t_kernel(const float* __restrict__ lb) {
    __shared__ float t[64][65];
    int g = blockIdx.y;
    int n0 = blockIdx.x * 64;
    for (int idx = threadIdx.x; idx < 4096; idx += 256) {
        int r = idx >> 6, n = idx & 63;
        t[n][r] = lb[((size_t)g * R_DIM + r) * N_DIM + n0 + n];
    }
    __syncthreads();
    for (int idx = threadIdx.x; idx < 4096; idx += 256) {
        int n = idx >> 6, r = idx & 63;
        g_lb16[((size_t)g * N_DIM + n0 + n) * R_DIM + r] = __float2half_rn(t[n][r]);
    }
}

// =============================================================================
// Shrink GEMM: shrink[8192,64] = x @ lora_a[g]^T, single fp16 term.
// CTA tile 128x64, 256 threads (8 warps: 4m x 2n, warp tile 32x32), BK=64.
// Stage: A(16K) B(8K) = 24KB; 4 stages = 96KB.
// =============================================================================
#define SH_STAGE 24576
#define SH_CHUNKS (K_DIM / 64)   // 64

__global__ __launch_bounds__(256, 1) void shrink_gemm(
    const int* __restrict__ gl, int n_groups)
{
    extern __shared__ char smem[];
    uint32_t sb = smem_u32(smem);
    int tid = threadIdx.x, lane = tid & 31, w = tid >> 5;
    int m_off = (w & 3) * 32, n_off = (w >> 2) * 32;
    int row0 = blockIdx.x * 128;
    int g = find_group(gl, n_groups, row0);

    const __half* A = g_x16 + (size_t)row0 * K_DIM;
    const __half* B = g_la16 + (size_t)g * R_DIM * K_DIM;

    float acc[2][4][4];
    #pragma unroll
    for (int i = 0; i < 2; i++)
        #pragma unroll
        for (int j = 0; j < 4; j++)
            #pragma unroll
            for (int q = 0; q < 4; q++) acc[i][j][q] = 0.f;

    // fill stage s with chunk c (k-offset c*64): 1536 16B items, 6 per thread
    auto fill = [&](int s, int c) {
        uint32_t st = sb + s * SH_STAGE;
        #pragma unroll
        for (int it = 0; it < 6; it++) {
            int idx = tid + it * 256;
            if (idx < 1024) {               // A: 128 rows x 8 ch
                int row = idx >> 3, ch = idx & 7;
                CP16(st + swz(row, ch),
                     A + (size_t)row * K_DIM + c * 64 + ch * 8);
            } else {                        // B: 64 rows x 8 ch
                int u = idx - 1024;
                int row = u >> 3, ch = u & 7;
                CP16(st + 16384 + swz(row, ch),
                     B + (size_t)row * K_DIM + c * 64 + ch * 8);
            }
        }
    };

    fill(0, 0); CP_COMMIT();
    fill(1, 1); CP_COMMIT();
    fill(2, 2); CP_COMMIT();

    for (int c = 0; c < SH_CHUNKS; c++) {
        CP_WAIT2();
        __syncthreads();
        uint32_t st = sb + (c & 3) * SH_STAGE;
        #pragma unroll
        for (int ks = 0; ks < 4; ks++) {
            uint32_t aa[2][4], bb[2][4];
            #pragma unroll
            for (int mt = 0; mt < 2; mt++) {
                int row = m_off + mt * 16 + (lane & 15);
                int ch = ks * 2 + (lane >> 4);
                LDSM4(aa[mt], st + swz(row, ch));
            }
            #pragma unroll
            for (int p = 0; p < 2; p++) {
                int row = n_off + p * 16 + (lane & 15);
                int ch = ks * 2 + (lane >> 4);
                LDSM4(bb[p], st + 16384 + swz(row, ch));
            }
            #pragma unroll
            for (int mt = 0; mt < 2; mt++)
                #pragma unroll
                for (int p = 0; p < 2; p++) {
                    MMA_F16(acc[mt][2 * p],     aa[mt], bb[p][0], bb[p][2]);
                    MMA_F16(acc[mt][2 * p + 1], aa[mt], bb[p][1], bb[p][3]);
                }
        }
        if (c + 3 < SH_CHUNKS) fill((c + 3) & 3, c + 3);
        CP_COMMIT();
    }

    #pragma unroll
    for (int mt = 0; mt < 2; mt++)
        #pragma unroll
        for (int j = 0; j < 4; j++) {
            int row = row0 + m_off + mt * 16 + (lane >> 2);
            int col = n_off + j * 8 + ((lane & 3) << 1);
            *reinterpret_cast<__half2*>(g_sh16 + (size_t)row * R_DIM + col)
                = __floats2half2_rn(acc[mt][j][0], acc[mt][j][1]);
            *reinterpret_cast<__half2*>(g_sh16 + (size_t)(row + 8) * R_DIM + col)
                = __floats2half2_rn(acc[mt][j][2], acc[mt][j][3]);
        }
}

// =============================================================================
// Main GEMM: out[8192,4096] = x @ W^T (+ fused LoRA expand over rank 64).
// CTA tile 128x256, 512 threads (16 warps: 4m x 4n, warp tile 32x64), BK=64.
// Stage: A(16K) B(32K) = 48KB; 4 stages = 192KB.
// Chunks: 64 base-K + 1 LoRA (rank 64 = exactly one BK=64 chunk).
// =============================================================================
#define MN_STAGE 49152
#define MN_CHUNKS (K_DIM / 64 + 1)   // 65

__global__ __launch_bounds__(512, 1) void gemm_main(
    const int* __restrict__ gl, int n_groups, float* __restrict__ out)
{
    extern __shared__ char smem[];
    uint32_t sb = smem_u32(smem);
    int tid = threadIdx.x, lane = tid & 31, w = tid >> 5;
    int m_off = (w & 3) * 32, n_off = (w >> 2) * 64;
    int row0 = blockIdx.y * 128;
    int col0 = blockIdx.x * 256;
    int g = find_group(gl, n_groups, row0);

    float acc[2][8][4];
    #pragma unroll
    for (int i = 0; i < 2; i++)
        #pragma unroll
        for (int j = 0; j < 8; j++)
            #pragma unroll
            for (int q = 0; q < 4; q++) acc[i][j][q] = 0.f;

    auto fill = [&](int s, int c) {
        uint32_t st = sb + s * MN_STAGE;
        const __half *pA, *pB;
        size_t lda, ldb;
        if (c < K_DIM / 64) {
            pA = g_x16 + (size_t)row0 * K_DIM + c * 64;
            pB = g_w16 + (size_t)col0 * K_DIM + c * 64;
            lda = K_DIM; ldb = K_DIM;
        } else {
            pA = g_sh16 + (size_t)row0 * R_DIM;
            pB = g_lb16 + ((size_t)g * N_DIM + col0) * R_DIM;
            lda = R_DIM; ldb = R_DIM;
        }
        #pragma unroll
        for (int it = 0; it < 6; it++) {
            int idx = tid + it * 512;
            if (idx < 1024) {               // A: 128 rows x 8 ch
                int row = idx >> 3, ch = idx & 7;
                CP16(st + swz(row, ch), pA + (size_t)row * lda + ch * 8);
            } else {                        // B: 256 rows x 8 ch
                int u = idx - 1024;
                int row = u >> 3, ch = u & 7;
                CP16(st + 16384 + swz(row, ch), pB + (size_t)row * ldb + ch * 8);
            }
        }
    };

    fill(0, 0); CP_COMMIT();
    fill(1, 1); CP_COMMIT();
    fill(2, 2); CP_COMMIT();

    for (int c = 0; c < MN_CHUNKS; c++) {
        CP_WAIT2();
        __syncthreads();
        uint32_t st = sb + (c & 3) * MN_STAGE;
        #pragma unroll
        for (int ks = 0; ks < 4; ks++) {
            uint32_t aa[2][4], bb[4][4];
            #pragma unroll
            for (int mt = 0; mt < 2; mt++) {
                int row = m_off + mt * 16 + (lane & 15);
                int ch = ks * 2 + (lane >> 4);
                LDSM4(aa[mt], st + swz(row, ch));
            }
            #pragma unroll
            for (int p = 0; p < 4; p++) {
                int row = n_off + p * 16 + (lane & 15);
                int ch = ks * 2 + (lane >> 4);
                LDSM4(bb[p], st + 16384 + swz(row, ch));
            }
            #pragma unroll
            for (int mt = 0; mt < 2; mt++)
                #pragma unroll
                for (int p = 0; p < 4; p++) {
                    MMA_F16(acc[mt][2 * p],     aa[mt], bb[p][0], bb[p][2]);
                    MMA_F16(acc[mt][2 * p + 1], aa[mt], bb[p][1], bb[p][3]);
                }
        }
        if (c + 3 < MN_CHUNKS) fill((c + 3) & 3, c + 3);
        CP_COMMIT();
    }

    #pragma unroll
    for (int mt = 0; mt < 2; mt++)
        #pragma unroll
        for (int j = 0; j < 8; j++) {
            int row = row0 + m_off + mt * 16 + (lane >> 2);
            int col = col0 + n_off + j * 8 + ((lane & 3) << 1);
            *reinterpret_cast<float2*>(out + (size_t)row * N_DIM + col)
                = make_float2(acc[mt][j][0], acc[mt][j][1]);
            *reinterpret_cast<float2*>(out + (size_t)(row + 8) * N_DIM + col)
                = make_float2(acc[mt][j][2], acc[mt][j][3]);
        }
}

// ---------------- launch -----------------------------------------------------
extern "C" void kernel_launch(void* const* d_in, const int* in_sizes, int n_in,
                              void* d_out, int out_size) {
    const float* x      = (const float*)d_in[0];
    const float* W      = (const float*)d_in[1];
    const float* lora_a = (const float*)d_in[2];
    const float* lora_b = (const float*)d_in[3];
    const int*   gl     = (const int*)d_in[4];
    const int n_groups  = in_sizes[4];
    float* out = (float*)d_out;

    cudaFuncSetAttribute(shrink_gemm, cudaFuncAttributeMaxDynamicSharedMemorySize,
                         4 * SH_STAGE);
    cudaFuncSetAttribute(gemm_main, cudaFuncAttributeMaxDynamicSharedMemorySize,
                         4 * MN_STAGE);

    cvt_x_kernel<<<(T_DIM * (size_t)K_DIM / 4) / 256, 256>>>(x);
    cvt_w_kernel<<<(N_DIM * (size_t)K_DIM / 4) / 256, 256>>>(W);
    cvt_la_kernel<<<((size_t)NGRP * R_DIM * K_DIM / 4) / 256, 256>>>(lora_a);
    lorab_t_kernel<<<dim3(N_DIM / 64, NGRP), 256>>>(lora_b);

    shrink_gemm<<<T_DIM / 128, 256, 4 * SH_STAGE>>>(gl, n_groups);
    gemm_main<<<dim3(N_DIM / 256, T_DIM / 128), 512, 4 * MN_STAGE>>>(
        gl, n_groups, out);
}